// round 3
// baseline (speedup 1.0000x reference)
#include <cuda_runtime.h>
#include <cstdint>
#include <math.h>

// CTRNN: B=128, N=512, T=1024, fp32.
// 16 INDEPENDENT clusters of 8 CTAs (one per batch-chunk of 8 rows).
// Rank r of a cluster owns hidden cols [r*64, r*64+64). J slice + whole vel
// slice live in SMEM for the full run. Per step: stage tanh(h) (L2 global
// exchange within cluster), FFMA2 GEMM, h update + tanh, DSMEM readout
// partials to rank 0, HW cluster barrier. No grid-wide sync anywhere.

#define T_STEPS 1024
#define BATCH   128
#define NH      512
#define DTC     0.02f

#define CL   8                 // cluster size = hidden chunks
#define BS   8                 // batch rows per cluster
#define IS   64                // hidden cols per CTA
#define NCTA ((BATCH / BS) * CL)   // 128
#define NTHR 256
#define KW   8                 // k-split across 8 warps
#define KCH  (NH / KW)         // 64
#define LDP  516               // padded smem row (floats)

// smem layout (float offsets)
#define OFF_J     0
#define OFF_TH    (OFF_J + IS * LDP)            // J: 64x516
#define OFF_RED   (OFF_TH + BS * LDP)           // th: 8x516
#define OFF_H     (OFF_RED + KW * BS * IS)      // red: 8x512
#define OFF_VEL   (OFF_H + BS * IS)             // h: 512
#define OFF_BM    (OFF_VEL + BS * T_STEPS)      // vel: 8x1024
#define OFF_WR    (OFF_BM + IS)
#define OFF_PART  (OFF_WR + IS)                 // 16 warp partials
#define OFF_RPART (OFF_PART + 16)               // rank0 recv: 2 x 8 x 8
#define SMEM_FLOATS (OFF_RPART + 2 * CL * BS)
#define SMEM_BYTES  (SMEM_FLOATS * 4)

__device__ float g_th[2][BATCH][NH];   // tanh(h) double buffer (per-cluster rows)

__device__ __forceinline__ unsigned long long ffma2(unsigned long long a,
                                                    unsigned long long b,
                                                    unsigned long long c) {
    unsigned long long d;
    asm("fma.rn.f32x2 %0, %1, %2, %3;" : "=l"(d) : "l"(a), "l"(b), "l"(c));
    return d;
}

__device__ __forceinline__ float2 unpack2(unsigned long long v) {
    float2 f;
    asm("mov.b64 {%0, %1}, %2;" : "=f"(f.x), "=f"(f.y) : "l"(v));
    return f;
}

// Store one float into rank 0's smem at the address corresponding to `local`.
__device__ __forceinline__ void st_rank0_f32(const float* local, float v) {
    uint32_t laddr = (uint32_t)__cvta_generic_to_shared((void*)local);
    uint32_t raddr;
    asm volatile("mapa.shared::cluster.u32 %0, %1, 0;" : "=r"(raddr) : "r"(laddr));
    asm volatile("st.shared::cluster.f32 [%0], %1;" :: "r"(raddr), "f"(v) : "memory");
}

extern "C" __global__ void __launch_bounds__(NTHR, 1) __cluster_dims__(CL, 1, 1)
ctrnn_cluster_kernel(const float* __restrict__ vel,
                     const float* __restrict__ J,
                     const float* __restrict__ Bmat,
                     const float* __restrict__ Wro,
                     float* __restrict__ out) {
    extern __shared__ float smem[];
    float* J_s   = smem + OFF_J;
    float* th_s  = smem + OFF_TH;
    float* red   = smem + OFF_RED;
    float* h_s   = smem + OFF_H;
    float* vel_s = smem + OFF_VEL;
    float* bm_s  = smem + OFF_BM;
    float* wr_s  = smem + OFF_WR;
    float* part_s = smem + OFF_PART;
    float* rpart = smem + OFF_RPART;   // [2][CL][BS], valid contents on rank 0

    const int tid  = threadIdx.x;
    const int rank = blockIdx.x % CL;       // hidden chunk (== cluster ctarank)
    const int grp  = blockIdx.x / CL;       // batch chunk
    const int b0   = grp * BS;
    const int i0   = rank * IS;

    // One-time loads: J slice [IS x NH], vel slice [BS x T], Bmat/Wro slices.
    for (int k4 = tid; k4 < IS * NH / 4; k4 += NTHR) {
        int idx = k4 * 4;
        int r = idx >> 9, c = idx & 511;
        *reinterpret_cast<float4*>(J_s + r * LDP + c) =
            *reinterpret_cast<const float4*>(J + (size_t)(i0 + r) * NH + c);
    }
    for (int k4 = tid; k4 < BS * T_STEPS / 4; k4 += NTHR) {
        int idx = k4 * 4;
        int r = idx >> 10, c = idx & 1023;
        *reinterpret_cast<float4*>(vel_s + r * T_STEPS + c) =
            *reinterpret_cast<const float4*>(vel + (size_t)(b0 + r) * T_STEPS + c);
    }
    if (tid < IS) {
        bm_s[tid] = Bmat[i0 + tid];
        wr_s[tid] = Wro[i0 + tid];
    }
    for (int k = tid; k < BS * IS; k += NTHR) h_s[k] = 0.0f;
    for (int k4 = tid; k4 < BS * NH / 4; k4 += NTHR) {   // th(t=0) = tanh(0) = 0
        int idx = k4 * 4;
        int r = idx >> 9, c = idx & 511;
        *reinterpret_cast<float4*>(th_s + r * LDP + c) = make_float4(0.f, 0.f, 0.f, 0.f);
    }
    __syncthreads();

    const int w     = tid >> 5;       // warp -> k chunk
    const int lane  = tid & 31;
    const int bg    = lane & 1;       // 2 b-groups   (rows bg + 2u, u=0..3)
    const int ig    = lane >> 1;      // 16 i-groups  (cols ig + 16v, v=0..3)
    const int kbase = w * KCH;

    for (int t = 0; t < T_STEPS; ++t) {
        const int p = t & 1;

        // Lagged readout: rank 0 writes out[:, t-1] from DSMEM-delivered partials.
        if (rank == 0 && t > 0 && tid < BS) {
            const float* rp = rpart + ((t - 1) & 1) * CL * BS;
            float s = 0.f;
            #pragma unroll
            for (int r = 0; r < CL; ++r) s += rp[r * BS + tid];
            out[(size_t)(b0 + tid) * T_STEPS + (t - 1)] = s;
        }

        // Stage tanh(h_{t-1}) for our batch slice (written by cluster peers).
        if (t > 0) {
            #pragma unroll
            for (int q = 0; q < 4; ++q) {
                int idx = (tid + q * NTHR) * 4;
                int r = idx >> 9, c = idx & 511;
                *reinterpret_cast<float4*>(th_s + r * LDP + c) =
                    *reinterpret_cast<const float4*>(&g_th[p][b0 + r][c]);
            }
        }
        __syncthreads();

        // GEMM: mv[b][i] = sum_j th[b][j] * J[i][j], k split over 8 warps,
        // 4b x 4i per-thread tile, packed fma.rn.f32x2 over j.
        unsigned long long acc0[4][4], acc1[4][4];
        #pragma unroll
        for (int u = 0; u < 4; ++u)
            #pragma unroll
            for (int v = 0; v < 4; ++v) { acc0[u][v] = 0ull; acc1[u][v] = 0ull; }

        #pragma unroll 4
        for (int jt = 0; jt < KCH; jt += 4) {
            const int j = kbase + jt;
            ulonglong2 av[4], bv[4];
            #pragma unroll
            for (int u = 0; u < 4; ++u)
                av[u] = *reinterpret_cast<const ulonglong2*>(th_s + (bg + 2 * u) * LDP + j);
            #pragma unroll
            for (int v = 0; v < 4; ++v)
                bv[v] = *reinterpret_cast<const ulonglong2*>(J_s + (ig + 16 * v) * LDP + j);
            #pragma unroll
            for (int u = 0; u < 4; ++u)
                #pragma unroll
                for (int v = 0; v < 4; ++v) {
                    acc0[u][v] = ffma2(av[u].x, bv[v].x, acc0[u][v]);
                    acc1[u][v] = ffma2(av[u].y, bv[v].y, acc1[u][v]);
                }
        }
        #pragma unroll
        for (int u = 0; u < 4; ++u)
            #pragma unroll
            for (int v = 0; v < 4; ++v) {
                float2 lo = unpack2(acc0[u][v]);
                float2 hi = unpack2(acc1[u][v]);
                red[w * (BS * IS) + (bg + 2 * u) * IS + (ig + 16 * v)] =
                    (lo.x + lo.y) + (hi.x + hi.y);
            }
        __syncthreads();

        // Reduce k partials, update h, tanh, publish th; warp-reduce readout.
        #pragma unroll
        for (int pass = 0; pass < 2; ++pass) {
            const int idx = tid + pass * NTHR;
            float s = 0.f;
            #pragma unroll
            for (int k = 0; k < KW; ++k) s += red[k * (BS * IS) + idx];
            const int b = idx >> 6, i = idx & 63;
            float h = h_s[idx] * (1.0f - DTC)
                    + DTC * (s + vel_s[b * T_STEPS + t] * bm_s[i]);
            h_s[idx] = h;
            float th = tanhf(h);
            g_th[p ^ 1][b0 + b][i0 + i] = th;
            float c = th * wr_s[i];
            #pragma unroll
            for (int off = 16; off > 0; off >>= 1)
                c += __shfl_xor_sync(0xffffffffu, c, off);
            if (lane == 0) part_s[pass * 8 + w] = c;   // warp w covers b=w>>1 (+4*pass), half (w&1)
        }
        __syncthreads();

        // Combine the two half-row sums per b and push to rank 0 via DSMEM.
        if (tid < BS) {
            const int b = tid, ps = b >> 2, base = (b & 3) * 2;
            float s = part_s[ps * 8 + base] + part_s[ps * 8 + base + 1];
            st_rank0_f32(rpart + p * CL * BS + rank * BS + b, s);
        }

        // HW cluster barrier: release (orders g_th STG + DSMEM stores) / acquire.
        asm volatile("barrier.cluster.arrive.aligned;" ::: "memory");
        asm volatile("barrier.cluster.wait.aligned;" ::: "memory");
    }

    // Flush readout for the final step.
    if (rank == 0 && tid < BS) {
        const float* rp = rpart + ((T_STEPS - 1) & 1) * CL * BS;
        float s = 0.f;
        #pragma unroll
        for (int r = 0; r < CL; ++r) s += rp[r * BS + tid];
        out[(size_t)(b0 + tid) * T_STEPS + (T_STEPS - 1)] = s;
    }
}

extern "C" void kernel_launch(void* const* d_in, const int* in_sizes, int n_in,
                              void* d_out, int out_size) {
    const float* vel  = (const float*)d_in[0];   // [128,1024,1]
    const float* J    = (const float*)d_in[1];   // [512,512]
    const float* Bmat = (const float*)d_in[2];   // [512,1]
    const float* Wro  = (const float*)d_in[3];   // [1,512]
    float* out = (float*)d_out;                  // [128,1024,1]

    cudaFuncSetAttribute(ctrnn_cluster_kernel,
                         cudaFuncAttributeMaxDynamicSharedMemorySize, SMEM_BYTES);
    ctrnn_cluster_kernel<<<NCTA, NTHR, SMEM_BYTES>>>(vel, J, Bmat, Wro, out);
}

// round 5
// speedup vs baseline: 1.0154x; 1.0154x over previous
#include <cuda_runtime.h>
#include <cstdint>
#include <math.h>

// CTRNN B=128, N=512, T=1024, fp32.
// 16 independent clusters of 8 CTAs; rank r owns hidden cols [r*64, r*64+64),
// cluster g owns batch rows [g*8, g*8+8). J slice + vel slice resident in SMEM.
// Per step: mbarrier full-wait (acquire.cluster) -> stage tanh(h) from L2
// (__ldcg) -> FFMA2 GEMM (k split over 16 warps) -> reduce + h update (h in
// registers) + tanh -> empty-wait -> __stcg publish -> remote mbarrier
// arrives (release.cluster). No cluster.sync in the loop, no atomics.
//
// R4 fix: full-barrier wait parity is ((t-1)>>1)&1 (R3 used (t>>1)&1, which
// deadlocked at t=2: full[0]'s first completion is parity 0, not 1).

#define T_STEPS 1024
#define BATCH   128
#define NH      512
#define DTC     0.02f

#define CL   8
#define BS   8
#define IS   64
#define NCTA 128
#define NTHR 512
#define KW   16                // k-chunks (one per warp)
#define KCH  (NH / KW)         // 32
#define LDP  516               // padded row stride (floats)

// smem layout (float offsets)
#define OFF_J     0
#define OFF_TH    (OFF_J + IS * LDP)          // 33024
#define OFF_RED   (OFF_TH + BS * LDP)         // 37152
#define OFF_VEL   (OFF_RED + KW * BS * IS)    // 45344
#define OFF_BM    (OFF_VEL + BS * T_STEPS)    // 53536
#define OFF_WR    (OFF_BM + IS)               // 53600
#define OFF_PART  (OFF_WR + IS)               // 53664
#define OFF_RPART (OFF_PART + 16)             // 53680
#define OFF_BARS  (OFF_RPART + 2 * CL * BS)   // 53808 (8B aligned)
#define SMEM_FLOATS (OFF_BARS + 8)            // 4 mbarriers = 8 floats
#define SMEM_BYTES  (SMEM_FLOATS * 4)         // ~215 KB

__device__ float g_th[2][BATCH][NH];   // tanh(h) double buffer (L2 exchange)

__device__ __forceinline__ unsigned long long ffma2(unsigned long long a,
                                                    unsigned long long b,
                                                    unsigned long long c) {
    unsigned long long d;
    asm("fma.rn.f32x2 %0, %1, %2, %3;" : "=l"(d) : "l"(a), "l"(b), "l"(c));
    return d;
}

__device__ __forceinline__ float2 unpack2(unsigned long long v) {
    float2 f;
    asm("mov.b64 {%0, %1}, %2;" : "=f"(f.x), "=f"(f.y) : "l"(v));
    return f;
}

__device__ __forceinline__ void mbar_init(uint32_t addr, uint32_t count) {
    asm volatile("mbarrier.init.shared.b64 [%0], %1;" :: "r"(addr), "r"(count) : "memory");
}

// Arrive (release.cluster) on the mbarrier at `local_addr`'s offset in CTA `target`.
__device__ __forceinline__ void mbar_arrive_remote(uint32_t local_addr, uint32_t target) {
    uint32_t raddr;
    asm volatile("mapa.shared::cluster.u32 %0, %1, %2;" : "=r"(raddr)
                 : "r"(local_addr), "r"(target));
    asm volatile("mbarrier.arrive.release.cluster.shared::cluster.b64 _, [%0];"
                 :: "r"(raddr) : "memory");
}

// Parity wait with acquire.cluster (covers peers' global + DSMEM stores).
__device__ __forceinline__ void mbar_wait(uint32_t addr, uint32_t parity) {
    uint32_t done;
    asm volatile(
        "{\n\t.reg .pred p;\n\t"
        "mbarrier.try_wait.parity.acquire.cluster.shared::cta.b64 p, [%1], %2;\n\t"
        "selp.b32 %0, 1, 0, p;\n\t}"
        : "=r"(done) : "r"(addr), "r"(parity) : "memory");
    if (!done) {
        asm volatile(
            "{\n\t.reg .pred P1;\n\t"
            "WL_%=:\n\t"
            "mbarrier.try_wait.parity.acquire.cluster.shared::cta.b64 P1, [%0], %1, 0x989680;\n\t"
            "@P1 bra.uni WD_%=;\n\t"
            "bra.uni WL_%=;\n\t"
            "WD_%=:\n\t}"
            :: "r"(addr), "r"(parity) : "memory");
    }
}

__device__ __forceinline__ void st_rank0_f32(const float* local, float v) {
    uint32_t laddr = (uint32_t)__cvta_generic_to_shared((void*)local);
    uint32_t raddr;
    asm volatile("mapa.shared::cluster.u32 %0, %1, 0;" : "=r"(raddr) : "r"(laddr));
    asm volatile("st.shared::cluster.f32 [%0], %1;" :: "r"(raddr), "f"(v) : "memory");
}

extern "C" __global__ void __launch_bounds__(NTHR, 1) __cluster_dims__(CL, 1, 1)
ctrnn_mbar_kernel(const float* __restrict__ vel,
                  const float* __restrict__ J,
                  const float* __restrict__ Bmat,
                  const float* __restrict__ Wro,
                  float* __restrict__ out) {
    extern __shared__ float smem[];
    float* J_s    = smem + OFF_J;
    float* th_s   = smem + OFF_TH;
    float* red    = smem + OFF_RED;
    float* vel_s  = smem + OFF_VEL;
    float* bm_s   = smem + OFF_BM;
    float* wr_s   = smem + OFF_WR;
    float* part_s = smem + OFF_PART;
    float* rpart  = smem + OFF_RPART;          // [2][CL][BS] (valid on rank 0)

    const uint32_t bars = (uint32_t)__cvta_generic_to_shared(smem + OFF_BARS);
    // full[q] at bars + q*8 ; empty[q] at bars + 16 + q*8

    const int tid  = threadIdx.x;
    const int rank = blockIdx.x & (CL - 1);
    const int grp  = blockIdx.x / CL;
    const int b0   = grp * BS;
    const int i0   = rank * IS;

    // One-time loads.
    for (int k4 = tid; k4 < IS * NH / 4; k4 += NTHR) {      // J slice 64x512
        int idx = k4 * 4, r = idx >> 9, c = idx & 511;
        *reinterpret_cast<float4*>(J_s + r * LDP + c) =
            *reinterpret_cast<const float4*>(J + (size_t)(i0 + r) * NH + c);
    }
    for (int k4 = tid; k4 < BS * T_STEPS / 4; k4 += NTHR) { // vel slice 8x1024
        int idx = k4 * 4, r = idx >> 10, c = idx & 1023;
        *reinterpret_cast<float4*>(vel_s + r * T_STEPS + c) =
            *reinterpret_cast<const float4*>(vel + (size_t)(b0 + r) * T_STEPS + c);
    }
    if (tid < IS) { bm_s[tid] = Bmat[i0 + tid]; wr_s[tid] = Wro[i0 + tid]; }
    for (int k4 = tid; k4 < BS * NH / 4; k4 += NTHR) {      // th(t=0) = 0
        int idx = k4 * 4, r = idx >> 9, c = idx & 511;
        *reinterpret_cast<float4*>(th_s + r * LDP + c) = make_float4(0.f, 0.f, 0.f, 0.f);
    }
    if (tid == 0) {
        mbar_init(bars + 0,  CL);  mbar_init(bars + 8,  CL);   // full[0], full[1]
        mbar_init(bars + 16, CL);  mbar_init(bars + 24, CL);   // empty[0], empty[1]
    }
    __syncthreads();
    asm volatile("barrier.cluster.arrive.aligned;" ::: "memory");
    asm volatile("barrier.cluster.wait.aligned;" ::: "memory");

    const int w = tid >> 5, lane = tid & 31;
    const int bg = lane & 1, ig = lane >> 1;
    const int kbase = w * KCH;
    const int b = tid >> 6, i = tid & 63;
    const float bmv = bm_s[i];
    const float wrv = wr_s[i];
    float h = 0.f;

    for (int t = 0; t < T_STEPS; ++t) {
        const int p = t & 1;
        // full[p] completes for the n-th time at the wait of step t, where
        // n = ceil(t/2); parity of n-th completion = (n-1)&1 = ((t-1)>>1)&1.
        const uint32_t wfull  = (uint32_t)((t - 1) >> 1) & 1u;
        // empty[p^1] completion parity at step t's publish wait (t>=2).
        const uint32_t wempty = (((uint32_t)(t >> 1) & 1u) ^ 1u);

        if (t > 0) {
            mbar_wait(bars + p * 8, wfull);

            // Stage tanh(h_{t-1}) slice (peers wrote via stcg; read L2 directly).
            const int a0 = tid * 4, r0 = a0 >> 9, c0 = a0 & 511;
            float4 s0 = __ldcg(reinterpret_cast<const float4*>(&g_th[p][b0 + r0][c0]));
            float4 s1 = __ldcg(reinterpret_cast<const float4*>(&g_th[p][b0 + r0 + 4][c0]));

            // Lagged readout: rank 0 writes out[:, t-1] (overlaps the loads).
            if (rank == 0 && tid < BS) {
                const float* rp = rpart + ((t - 1) & 1) * CL * BS;
                float s = 0.f;
                #pragma unroll
                for (int r = 0; r < CL; ++r) s += rp[r * BS + tid];
                out[(size_t)(b0 + tid) * T_STEPS + (t - 1)] = s;
            }

            *reinterpret_cast<float4*>(th_s + r0 * LDP + c0) = s0;
            *reinterpret_cast<float4*>(th_s + (r0 + 4) * LDP + c0) = s1;
        }
        __syncthreads();
        // th_s consumed into local smem: peers may overwrite g_th[p].
        if (t > 0 && tid < CL) mbar_arrive_remote(bars + 16 + p * 8, (uint32_t)tid);

        // GEMM: red[w][b][i] = sum_{j in chunk w} th[b][j] * J[i][j]
        unsigned long long acc[4][4];
        #pragma unroll
        for (int u = 0; u < 4; ++u)
            #pragma unroll
            for (int v = 0; v < 4; ++v) acc[u][v] = 0ull;

        #pragma unroll
        for (int jt = 0; jt < KCH; jt += 4) {
            const int j = kbase + jt;
            ulonglong2 av[4], bv[4];
            #pragma unroll
            for (int u = 0; u < 4; ++u)
                av[u] = *reinterpret_cast<const ulonglong2*>(th_s + (bg + 2 * u) * LDP + j);
            #pragma unroll
            for (int v = 0; v < 4; ++v)
                bv[v] = *reinterpret_cast<const ulonglong2*>(J_s + (ig + 16 * v) * LDP + j);
            #pragma unroll
            for (int u = 0; u < 4; ++u)
                #pragma unroll
                for (int v = 0; v < 4; ++v) {
                    acc[u][v] = ffma2(av[u].x, bv[v].x, acc[u][v]);
                    acc[u][v] = ffma2(av[u].y, bv[v].y, acc[u][v]);
                }
        }
        #pragma unroll
        for (int u = 0; u < 4; ++u)
            #pragma unroll
            for (int v = 0; v < 4; ++v) {
                float2 f2 = unpack2(acc[u][v]);
                red[w * (BS * IS) + (bg + 2 * u) * IS + (ig + 16 * v)] = f2.x + f2.y;
            }
        __syncthreads();

        // k-reduce (one element per thread), h update, tanh, readout partial.
        float rsum;
        {
            float rk[KW];
            #pragma unroll
            for (int k = 0; k < KW; ++k) rk[k] = red[k * (BS * IS) + tid];
            #pragma unroll
            for (int stp = 1; stp < KW; stp <<= 1)
                #pragma unroll
                for (int k = 0; k < KW; k += 2 * stp) rk[k] += rk[k + stp];
            rsum = rk[0];
        }
        h = h * (1.0f - DTC) + DTC * (rsum + vel_s[b * T_STEPS + t] * bmv);
        const float th = tanhf(h);

        float c = th * wrv;
        #pragma unroll
        for (int off = 16; off > 0; off >>= 1)
            c += __shfl_xor_sync(0xffffffffu, c, off);
        if (lane == 0) part_s[w] = c;   // warp w: b = w>>1, i-half = w&1

        // Publish th for step t+1 into g_th[p^1] (wait writers' buffer free).
        if (t < T_STEPS - 1) {
            if (t >= 2) mbar_wait(bars + 16 + (p ^ 1) * 8, wempty);
            __stcg(&g_th[p ^ 1][b0 + b][i0 + i], th);
        }
        __syncthreads();
        if (tid < BS) {
            float s = part_s[2 * tid] + part_s[2 * tid + 1];
            st_rank0_f32(rpart + p * CL * BS + rank * BS + tid, s);
        }
        __syncthreads();
        if (t < T_STEPS - 1 && tid < CL)
            mbar_arrive_remote(bars + (p ^ 1) * 8, (uint32_t)tid);
    }

    // Final-step readout flush.
    asm volatile("barrier.cluster.arrive.aligned;" ::: "memory");
    asm volatile("barrier.cluster.wait.aligned;" ::: "memory");
    if (rank == 0 && tid < BS) {
        const float* rp = rpart + ((T_STEPS - 1) & 1) * CL * BS;
        float s = 0.f;
        #pragma unroll
        for (int r = 0; r < CL; ++r) s += rp[r * BS + tid];
        out[(size_t)(b0 + tid) * T_STEPS + (T_STEPS - 1)] = s;
    }
}

extern "C" void kernel_launch(void* const* d_in, const int* in_sizes, int n_in,
                              void* d_out, int out_size) {
    const float* vel  = (const float*)d_in[0];   // [128,1024,1]
    const float* J    = (const float*)d_in[1];   // [512,512]
    const float* Bmat = (const float*)d_in[2];   // [512,1]
    const float* Wro  = (const float*)d_in[3];   // [1,512]
    float* out = (float*)d_out;                  // [128,1024,1]

    cudaFuncSetAttribute(ctrnn_mbar_kernel,
                         cudaFuncAttributeMaxDynamicSharedMemorySize, SMEM_BYTES);
    ctrnn_mbar_kernel<<<NCTA, NTHR, SMEM_BYTES>>>(vel, J, Bmat, Wro, out);
}

// round 6
// speedup vs baseline: 1.1167x; 1.0997x over previous
#include <cuda_runtime.h>
#include <cstdint>
#include <math.h>

// CTRNN B=128, N=512, T=1024, fp32. 16 independent clusters of 8 CTAs.
// Rank r owns hidden cols [r*64, 64); cluster g owns batch rows [g*8, 8).
// R6: 256 threads, k-split 8, 2 syncthreads/step, warp-owns-batch-row reduce
// (shuffle readout, no part_s pass), hoisted empty-wait, fast tanh, padded red.

#define T_STEPS 1024
#define BATCH   128
#define NH      512
#define DTC     0.02f

#define CL   8
#define BS   8
#define IS   64
#define NCTA 128
#define NTHR 256
#define KW   8                 // k-chunks (one per warp)
#define KCH  64
#define LDP  516               // padded row stride (floats)
#define RB   80                // red row pad (conflict-free STS)

// smem float offsets
#define OFF_J     0                            // 64*516 = 33024
#define OFF_TH    (OFF_J + IS * LDP)           // 8*516  -> 37152
#define OFF_RED   (OFF_TH + BS * LDP)          // 8*8*80 -> 42272
#define OFF_VEL   (OFF_RED + KW * BS * RB)     // 8*1024 -> 50464
#define OFF_RPART (OFF_VEL + BS * T_STEPS)     // 2*64   -> 50592
#define OFF_BARS  (OFF_RPART + 2 * CL * BS)    // 8B-aligned
#define SMEM_FLOATS (OFF_BARS + 8)
#define SMEM_BYTES  (SMEM_FLOATS * 4)          // ~198 KB

__device__ float g_th[2][BATCH][NH];   // tanh(h) double buffer (L2 exchange)

__device__ __forceinline__ unsigned long long ffma2(unsigned long long a,
                                                    unsigned long long b,
                                                    unsigned long long c) {
    unsigned long long d;
    asm("fma.rn.f32x2 %0, %1, %2, %3;" : "=l"(d) : "l"(a), "l"(b), "l"(c));
    return d;
}

__device__ __forceinline__ float2 unpack2(unsigned long long v) {
    float2 f;
    asm("mov.b64 {%0, %1}, %2;" : "=f"(f.x), "=f"(f.y) : "l"(v));
    return f;
}

__device__ __forceinline__ float fast_tanh(float x) {
    // tanh(x) = 1 - 2/(e^{2x}+1); ex2.approx + rcp.approx, rel err ~1e-6.
    float e = __expf(2.0f * x);
    return 1.0f - __fdividef(2.0f, e + 1.0f);
}

__device__ __forceinline__ void mbar_init(uint32_t addr, uint32_t count) {
    asm volatile("mbarrier.init.shared.b64 [%0], %1;" :: "r"(addr), "r"(count) : "memory");
}

__device__ __forceinline__ void mbar_arrive_remote(uint32_t local_addr, uint32_t target) {
    uint32_t raddr;
    asm volatile("mapa.shared::cluster.u32 %0, %1, %2;" : "=r"(raddr)
                 : "r"(local_addr), "r"(target));
    asm volatile("mbarrier.arrive.release.cluster.shared::cluster.b64 _, [%0];"
                 :: "r"(raddr) : "memory");
}

__device__ __forceinline__ void mbar_wait(uint32_t addr, uint32_t parity) {
    uint32_t done;
    asm volatile(
        "{\n\t.reg .pred p;\n\t"
        "mbarrier.try_wait.parity.acquire.cluster.shared::cta.b64 p, [%1], %2;\n\t"
        "selp.b32 %0, 1, 0, p;\n\t}"
        : "=r"(done) : "r"(addr), "r"(parity) : "memory");
    if (!done) {
        asm volatile(
            "{\n\t.reg .pred P1;\n\t"
            "WL_%=:\n\t"
            "mbarrier.try_wait.parity.acquire.cluster.shared::cta.b64 P1, [%0], %1, 0x989680;\n\t"
            "@P1 bra.uni WD_%=;\n\t"
            "bra.uni WL_%=;\n\t"
            "WD_%=:\n\t}"
            :: "r"(addr), "r"(parity) : "memory");
    }
}

__device__ __forceinline__ void st_rank0_f32(const float* local, float v) {
    uint32_t laddr = (uint32_t)__cvta_generic_to_shared((void*)local);
    uint32_t raddr;
    asm volatile("mapa.shared::cluster.u32 %0, %1, 0;" : "=r"(raddr) : "r"(laddr));
    asm volatile("st.shared::cluster.f32 [%0], %1;" :: "r"(raddr), "f"(v) : "memory");
}

extern "C" __global__ void __launch_bounds__(NTHR, 1) __cluster_dims__(CL, 1, 1)
ctrnn_r6_kernel(const float* __restrict__ vel,
                const float* __restrict__ J,
                const float* __restrict__ Bmat,
                const float* __restrict__ Wro,
                float* __restrict__ out) {
    extern __shared__ float smem[];
    float* J_s   = smem + OFF_J;
    float* th_s  = smem + OFF_TH;
    float* red   = smem + OFF_RED;     // red[k][b][i] at k*(BS*RB) + b*RB + i
    float* vel_s = smem + OFF_VEL;
    float* rpart = smem + OFF_RPART;   // [2][CL][BS] valid on rank 0

    const uint32_t bars = (uint32_t)__cvta_generic_to_shared(smem + OFF_BARS);
    // full[q] @ bars + q*8 (count 64); empty[q] @ bars + 16 + q*8 (count 8)

    const int tid  = threadIdx.x;
    const int rank = blockIdx.x & (CL - 1);
    const int grp  = blockIdx.x / CL;
    const int b0   = grp * BS;
    const int i0   = rank * IS;

    // One-time loads.
    for (int k4 = tid; k4 < IS * NH / 4; k4 += NTHR) {      // J slice 64x512
        int idx = k4 * 4, r = idx >> 9, c = idx & 511;
        *reinterpret_cast<float4*>(J_s + r * LDP + c) =
            *reinterpret_cast<const float4*>(J + (size_t)(i0 + r) * NH + c);
    }
    for (int k4 = tid; k4 < BS * T_STEPS / 4; k4 += NTHR) { // vel slice 8x1024
        int idx = k4 * 4, r = idx >> 10, c = idx & 1023;
        *reinterpret_cast<float4*>(vel_s + r * T_STEPS + c) =
            *reinterpret_cast<const float4*>(vel + (size_t)(b0 + r) * T_STEPS + c);
    }
    for (int k4 = tid; k4 < BS * NH / 4; k4 += NTHR) {      // th(t=0) = 0
        int idx = k4 * 4, r = idx >> 9, c = idx & 511;
        *reinterpret_cast<float4*>(th_s + r * LDP + c) = make_float4(0.f, 0.f, 0.f, 0.f);
    }
    if (tid == 0) {
        mbar_init(bars + 0,  64); mbar_init(bars + 8,  64);  // full[0..1]
        mbar_init(bars + 16, 8);  mbar_init(bars + 24, 8);   // empty[0..1]
    }
    __syncthreads();
    asm volatile("barrier.cluster.arrive.aligned;" ::: "memory");
    asm volatile("barrier.cluster.wait.aligned;" ::: "memory");

    const int w = tid >> 5, lane = tid & 31;
    const int bg = lane & 1, ig = lane >> 1;    // GEMM tile coords
    const int kbase = w * KCH;

    // Reduce-phase ownership: warp w owns batch row b=w, i = lane and lane+32.
    const float bm1 = Bmat[i0 + lane];
    const float bm2 = Bmat[i0 + lane + 32];
    const float wr1 = Wro[i0 + lane];
    const float wr2 = Wro[i0 + lane + 32];
    float h1 = 0.f, h2 = 0.f;

    for (int t = 0; t < T_STEPS; ++t) {
        const int p = t & 1;
        const uint32_t wfull  = (uint32_t)((t - 1) >> 1) & 1u;   // full[p] parity
        const uint32_t wempty = (((uint32_t)(t >> 1) & 1u) ^ 1u); // empty[p^1] parity

        if (t > 0) {
            mbar_wait(bars + p * 8, wfull);          // peers' th + rpart ready
            if (t >= 2) mbar_wait(bars + 16 + (p ^ 1) * 8, wempty);  // buffer free (cheap)

            // Stage tanh(h_{t-1}) slice from L2 (4 x LDG.128 per thread, batched).
            float4 s[4];
            #pragma unroll
            for (int q = 0; q < 4; ++q) {
                int idx = (tid + q * NTHR) * 4, r = idx >> 9, c = idx & 511;
                s[q] = __ldcg(reinterpret_cast<const float4*>(&g_th[p][b0 + r][c]));
            }
            // Lagged readout: rank 0 writes out[:, t-1] (overlaps LDG latency).
            if (rank == 0 && tid < BS) {
                const float* rp = rpart + ((t - 1) & 1) * CL * BS;
                float sum = 0.f;
                #pragma unroll
                for (int r = 0; r < CL; ++r) sum += rp[r * BS + tid];
                out[(size_t)(b0 + tid) * T_STEPS + (t - 1)] = sum;
            }
            #pragma unroll
            for (int q = 0; q < 4; ++q) {
                int idx = (tid + q * NTHR) * 4, r = idx >> 9, c = idx & 511;
                *reinterpret_cast<float4*>(th_s + r * LDP + c) = s[q];
            }
        }
        __syncthreads();                                   // SYNC 1
        if (t > 0 && tid < CL)                             // g_th[p] consumed
            mbar_arrive_remote(bars + 16 + p * 8, (uint32_t)tid);

        // GEMM: red[w][b][i] = sum_{j in chunk w} th[b][j] * J[i][j]
        unsigned long long acc[4][4];
        #pragma unroll
        for (int u = 0; u < 4; ++u)
            #pragma unroll
            for (int v = 0; v < 4; ++v) acc[u][v] = 0ull;

        #pragma unroll
        for (int jt = 0; jt < KCH; jt += 4) {
            const int j = kbase + jt;
            ulonglong2 av[4], bv[4];
            #pragma unroll
            for (int u = 0; u < 4; ++u)
                av[u] = *reinterpret_cast<const ulonglong2*>(th_s + (bg + 2 * u) * LDP + j);
            #pragma unroll
            for (int v = 0; v < 4; ++v)
                bv[v] = *reinterpret_cast<const ulonglong2*>(J_s + (ig + 16 * v) * LDP + j);
            #pragma unroll
            for (int u = 0; u < 4; ++u)
                #pragma unroll
                for (int v = 0; v < 4; ++v) {
                    acc[u][v] = ffma2(av[u].x, bv[v].x, acc[u][v]);
                    acc[u][v] = ffma2(av[u].y, bv[v].y, acc[u][v]);
                }
        }
        #pragma unroll
        for (int u = 0; u < 4; ++u)
            #pragma unroll
            for (int v = 0; v < 4; ++v) {
                float2 f2 = unpack2(acc[u][v]);
                red[w * (BS * RB) + (bg + 2 * u) * RB + (ig + 16 * v)] = f2.x + f2.y;
            }
        __syncthreads();                                   // SYNC 2

        // k-reduce: warp w owns batch row w; lanes cover i = lane, lane+32.
        float s1 = 0.f, s2 = 0.f;
        #pragma unroll
        for (int k = 0; k < KW; ++k) {
            s1 += red[k * (BS * RB) + w * RB + lane];
            s2 += red[k * (BS * RB) + w * RB + lane + 32];
        }
        const float vt = vel_s[w * T_STEPS + t];
        h1 = h1 * (1.0f - DTC) + DTC * (s1 + vt * bm1);
        h2 = h2 * (1.0f - DTC) + DTC * (s2 + vt * bm2);
        const float th1 = fast_tanh(h1);
        const float th2 = fast_tanh(h2);

        // Publish th for step t+1 (buffer freeness guaranteed by hoisted wait).
        if (t < T_STEPS - 1) {
            __stcg(&g_th[p ^ 1][b0 + w][i0 + lane], th1);
            __stcg(&g_th[p ^ 1][b0 + w][i0 + lane + 32], th2);
        }

        // Readout partial for row b=w: warp shuffle, lane 0 -> rank 0 DSMEM.
        float c = th1 * wr1 + th2 * wr2;
        #pragma unroll
        for (int off = 16; off > 0; off >>= 1)
            c += __shfl_xor_sync(0xffffffffu, c, off);
        if (lane == 0)
            st_rank0_f32(rpart + p * CL * BS + rank * BS + w, c);

        // Per-warp full arrives (release orders this warp's stcg + DSMEM store).
        if (t < T_STEPS - 1 && lane < CL)
            mbar_arrive_remote(bars + (p ^ 1) * 8, (uint32_t)lane);
    }

    // Final-step readout flush.
    asm volatile("barrier.cluster.arrive.aligned;" ::: "memory");
    asm volatile("barrier.cluster.wait.aligned;" ::: "memory");
    if (rank == 0 && tid < BS) {
        const float* rp = rpart + ((T_STEPS - 1) & 1) * CL * BS;
        float s = 0.f;
        #pragma unroll
        for (int r = 0; r < CL; ++r) s += rp[r * BS + tid];
        out[(size_t)(b0 + tid) * T_STEPS + (T_STEPS - 1)] = s;
    }
}

extern "C" void kernel_launch(void* const* d_in, const int* in_sizes, int n_in,
                              void* d_out, int out_size) {
    const float* vel  = (const float*)d_in[0];   // [128,1024,1]
    const float* J    = (const float*)d_in[1];   // [512,512]
    const float* Bmat = (const float*)d_in[2];   // [512,1]
    const float* Wro  = (const float*)d_in[3];   // [1,512]
    float* out = (float*)d_out;                  // [128,1024,1]

    cudaFuncSetAttribute(ctrnn_r6_kernel,
                         cudaFuncAttributeMaxDynamicSharedMemorySize, SMEM_BYTES);
    ctrnn_r6_kernel<<<NCTA, NTHR, SMEM_BYTES>>>(vel, J, Bmat, Wro, out);
}

// round 7
// speedup vs baseline: 1.1923x; 1.0677x over previous
#include <cuda_runtime.h>
#include <cstdint>
#include <math.h>

// CTRNN B=128, N=512, T=1024, fp32. 16 independent clusters of 8 CTAs.
// Rank r owns hidden cols [r*64, r*64+64); cluster g owns batch rows [g*8,+8).
// R7: PER-WARP exchange pipeline. k-split warp w consumes exactly rank w's
// th slice -> 8 per-rank full barriers (count=1). Each warp waits only for
// its own slice, stages it itself (4xLDG.128 + 4xSTS.128 + syncwarp), and
// GEMMs independently. Own slice staged via STS at publish (no wait).
// 2 syncthreads/step; arrives from warp 0 post-sync (cumulative release).

#define T_STEPS 1024
#define BATCH   128
#define NH      512
#define DTC     0.02f

#define CL   8
#define BS   8
#define IS   64
#define NCTA 128
#define NTHR 256
#define KW   8
#define KCH  64
#define LDP  516
#define RB   80

// smem float offsets
#define OFF_J     0                            // 64*516
#define OFF_TH    (OFF_J + IS * LDP)
#define OFF_RED   (OFF_TH + BS * LDP)
#define OFF_VEL   (OFF_RED + KW * BS * RB)
#define OFF_RPART (OFF_VEL + BS * T_STEPS)     // [2][CL][BS]
#define OFF_BARS  (OFF_RPART + 2 * CL * BS)    // 8 mbarriers (8B each)
#define SMEM_FLOATS (OFF_BARS + 16)
#define SMEM_BYTES  (SMEM_FLOATS * 4)

__device__ float g_th[2][BATCH][NH];   // tanh(h) double buffer (L2 exchange)

__device__ __forceinline__ unsigned long long ffma2(unsigned long long a,
                                                    unsigned long long b,
                                                    unsigned long long c) {
    unsigned long long d;
    asm("fma.rn.f32x2 %0, %1, %2, %3;" : "=l"(d) : "l"(a), "l"(b), "l"(c));
    return d;
}

__device__ __forceinline__ float2 unpack2(unsigned long long v) {
    float2 f;
    asm("mov.b64 {%0, %1}, %2;" : "=f"(f.x), "=f"(f.y) : "l"(v));
    return f;
}

__device__ __forceinline__ float fast_tanh(float x) {
    float e = __expf(2.0f * x);
    return 1.0f - __fdividef(2.0f, e + 1.0f);
}

__device__ __forceinline__ void mbar_init(uint32_t addr, uint32_t count) {
    asm volatile("mbarrier.init.shared.b64 [%0], %1;" :: "r"(addr), "r"(count) : "memory");
}

__device__ __forceinline__ void mbar_arrive_remote(uint32_t local_addr, uint32_t target) {
    uint32_t raddr;
    asm volatile("mapa.shared::cluster.u32 %0, %1, %2;" : "=r"(raddr)
                 : "r"(local_addr), "r"(target));
    asm volatile("mbarrier.arrive.release.cluster.shared::cluster.b64 _, [%0];"
                 :: "r"(raddr) : "memory");
}

__device__ __forceinline__ void mbar_wait(uint32_t addr, uint32_t parity) {
    uint32_t done;
    asm volatile(
        "{\n\t.reg .pred p;\n\t"
        "mbarrier.try_wait.parity.acquire.cluster.shared::cta.b64 p, [%1], %2;\n\t"
        "selp.b32 %0, 1, 0, p;\n\t}"
        : "=r"(done) : "r"(addr), "r"(parity) : "memory");
    if (!done) {
        asm volatile(
            "{\n\t.reg .pred P1;\n\t"
            "WL_%=:\n\t"
            "mbarrier.try_wait.parity.acquire.cluster.shared::cta.b64 P1, [%0], %1, 0x989680;\n\t"
            "@P1 bra.uni WD_%=;\n\t"
            "bra.uni WL_%=;\n\t"
            "WD_%=:\n\t}"
            :: "r"(addr), "r"(parity) : "memory");
    }
}

__device__ __forceinline__ void st_rank0_f32(const float* local, float v) {
    uint32_t laddr = (uint32_t)__cvta_generic_to_shared((void*)local);
    uint32_t raddr;
    asm volatile("mapa.shared::cluster.u32 %0, %1, 0;" : "=r"(raddr) : "r"(laddr));
    asm volatile("st.shared::cluster.f32 [%0], %1;" :: "r"(raddr), "f"(v) : "memory");
}

extern "C" __global__ void __launch_bounds__(NTHR, 1) __cluster_dims__(CL, 1, 1)
ctrnn_r7_kernel(const float* __restrict__ vel,
                const float* __restrict__ J,
                const float* __restrict__ Bmat,
                const float* __restrict__ Wro,
                float* __restrict__ out) {
    extern __shared__ float smem[];
    float* J_s   = smem + OFF_J;
    float* th_s  = smem + OFF_TH;
    float* red   = smem + OFF_RED;
    float* vel_s = smem + OFF_VEL;
    float* rpart = smem + OFF_RPART;

    const uint32_t bars = (uint32_t)__cvta_generic_to_shared(smem + OFF_BARS);
    // full[c] @ bars + c*8, count = 1 (single releasing arrive per step)

    const int tid  = threadIdx.x;
    const int rank = blockIdx.x & (CL - 1);
    const int grp  = blockIdx.x / CL;
    const int b0   = grp * BS;
    const int i0   = rank * IS;

    // One-time loads.
    for (int k4 = tid; k4 < IS * NH / 4; k4 += NTHR) {
        int idx = k4 * 4, r = idx >> 9, c = idx & 511;
        *reinterpret_cast<float4*>(J_s + r * LDP + c) =
            *reinterpret_cast<const float4*>(J + (size_t)(i0 + r) * NH + c);
    }
    for (int k4 = tid; k4 < BS * T_STEPS / 4; k4 += NTHR) {
        int idx = k4 * 4, r = idx >> 10, c = idx & 1023;
        *reinterpret_cast<float4*>(vel_s + r * T_STEPS + c) =
            *reinterpret_cast<const float4*>(vel + (size_t)(b0 + r) * T_STEPS + c);
    }
    for (int k4 = tid; k4 < BS * NH / 4; k4 += NTHR) {      // th(t=0) = 0
        int idx = k4 * 4, r = idx >> 9, c = idx & 511;
        *reinterpret_cast<float4*>(th_s + r * LDP + c) = make_float4(0.f, 0.f, 0.f, 0.f);
    }
    if (tid < CL) mbar_init(bars + tid * 8, 1);
    __syncthreads();
    asm volatile("barrier.cluster.arrive.aligned;" ::: "memory");
    asm volatile("barrier.cluster.wait.aligned;" ::: "memory");

    const int w = tid >> 5, lane = tid & 31;
    const int bg = lane & 1, ig = lane >> 1;
    const int kbase = w * KCH;               // warp w <-> rank w's slice

    // Reduce-phase: warp w owns batch row b=w; i = lane, lane+32.
    const float bm1 = Bmat[i0 + lane];
    const float bm2 = Bmat[i0 + lane + 32];
    const float wr1 = Wro[i0 + lane];
    const float wr2 = Wro[i0 + lane + 32];
    float h1 = 0.f, h2 = 0.f;

    for (int t = 0; t < T_STEPS; ++t) {
        // ---- per-warp wait + stage of slice w (skip own slice & t=0) ----
        if (t > 0 && w != rank) {
            mbar_wait(bars + w * 8, (uint32_t)(t - 1) & 1u);
            const float* src = &g_th[(t - 1) & 1][b0][0];
            #pragma unroll
            for (int q = 0; q < 4; ++q) {
                int idx = lane + 32 * q;          // 0..127
                int row = idx >> 4, col = kbase + (idx & 15) * 4;
                float4 v4 = __ldcg(reinterpret_cast<const float4*>(src + (size_t)row * NH + col));
                *reinterpret_cast<float4*>(th_s + row * LDP + col) = v4;
            }
            __syncwarp();
        }

        // ---- GEMM: red[w][b][i] = sum_{j in slice w} th[b][j] * J[i][j] ----
        unsigned long long acc[4][4];
        #pragma unroll
        for (int u = 0; u < 4; ++u)
            #pragma unroll
            for (int v = 0; v < 4; ++v) acc[u][v] = 0ull;

        #pragma unroll
        for (int jt = 0; jt < KCH; jt += 4) {
            const int j = kbase + jt;
            ulonglong2 av[4], bv[4];
            #pragma unroll
            for (int u = 0; u < 4; ++u)
                av[u] = *reinterpret_cast<const ulonglong2*>(th_s + (bg + 2 * u) * LDP + j);
            #pragma unroll
            for (int v = 0; v < 4; ++v)
                bv[v] = *reinterpret_cast<const ulonglong2*>(J_s + (ig + 16 * v) * LDP + j);
            #pragma unroll
            for (int u = 0; u < 4; ++u)
                #pragma unroll
                for (int v = 0; v < 4; ++v) {
                    acc[u][v] = ffma2(av[u].x, bv[v].x, acc[u][v]);
                    acc[u][v] = ffma2(av[u].y, bv[v].y, acc[u][v]);
                }
        }
        #pragma unroll
        for (int u = 0; u < 4; ++u)
            #pragma unroll
            for (int v = 0; v < 4; ++v) {
                float2 f2 = unpack2(acc[u][v]);
                red[w * (BS * RB) + (bg + 2 * u) * RB + (ig + 16 * v)] = f2.x + f2.y;
            }
        __syncthreads();                                   // SYNC A

        // ---- reduce + h update + tanh;  rank0 lagged out write ----
        if (rank == 0 && t > 0 && tid < BS) {
            const float* rp = rpart + ((t - 1) & 1) * CL * BS;
            float s = 0.f;
            #pragma unroll
            for (int r = 0; r < CL; ++r) s += rp[r * BS + tid];
            out[(size_t)(b0 + tid) * T_STEPS + (t - 1)] = s;
        }

        float s1 = 0.f, s2 = 0.f;
        #pragma unroll
        for (int k = 0; k < KW; ++k) {
            s1 += red[k * (BS * RB) + w * RB + lane];
            s2 += red[k * (BS * RB) + w * RB + lane + 32];
        }
        const float vt = vel_s[w * T_STEPS + t];
        h1 = h1 * (1.0f - DTC) + DTC * (s1 + vt * bm1);
        h2 = h2 * (1.0f - DTC) + DTC * (s2 + vt * bm2);
        const float th1 = fast_tanh(h1);
        const float th2 = fast_tanh(h2);

        // ---- publish ----
        // Own slice direct to th_s (consumed by warp `rank` next step).
        th_s[w * LDP + i0 + lane]      = th1;
        th_s[w * LDP + i0 + lane + 32] = th2;
        if (t < T_STEPS - 1) {
            __stcg(&g_th[t & 1][b0 + w][i0 + lane], th1);
            __stcg(&g_th[t & 1][b0 + w][i0 + lane + 32], th2);
        }
        // Readout partial for row w.
        float c = th1 * wr1 + th2 * wr2;
        #pragma unroll
        for (int off = 16; off > 0; off >>= 1)
            c += __shfl_xor_sync(0xffffffffu, c, off);
        if (lane == 0)
            st_rank0_f32(rpart + (t & 1) * CL * BS + rank * BS + w, c);

        __syncthreads();                                   // SYNC B
        // Single releasing arrive per peer (cumulative over SYNC B).
        if (t < T_STEPS - 1 && w == 0 && lane < CL && lane != rank)
            mbar_arrive_remote(bars + rank * 8, (uint32_t)lane);
    }

    // Final-step readout flush.
    asm volatile("barrier.cluster.arrive.aligned;" ::: "memory");
    asm volatile("barrier.cluster.wait.aligned;" ::: "memory");
    if (rank == 0 && tid < BS) {
        const float* rp = rpart + ((T_STEPS - 1) & 1) * CL * BS;
        float s = 0.f;
        #pragma unroll
        for (int r = 0; r < CL; ++r) s += rp[r * BS + tid];
        out[(size_t)(b0 + tid) * T_STEPS + (T_STEPS - 1)] = s;
    }
}

extern "C" void kernel_launch(void* const* d_in, const int* in_sizes, int n_in,
                              void* d_out, int out_size) {
    const float* vel  = (const float*)d_in[0];   // [128,1024,1]
    const float* J    = (const float*)d_in[1];   // [512,512]
    const float* Bmat = (const float*)d_in[2];   // [512,1]
    const float* Wro  = (const float*)d_in[3];   // [1,512]
    float* out = (float*)d_out;                  // [128,1024,1]

    cudaFuncSetAttribute(ctrnn_r7_kernel,
                         cudaFuncAttributeMaxDynamicSharedMemorySize, SMEM_BYTES);
    ctrnn_r7_kernel<<<NCTA, NTHR, SMEM_BYTES>>>(vel, J, Bmat, Wro, out);
}